// round 16
// baseline (speedup 1.0000x reference)
#include <cuda_runtime.h>

// Problem constants (fixed for this problem instance)
#define NN 200000
#define EE 1600000
#define UU 20000
#define DD 64
#define EPS 0.1f

#define CAP 64   // per-dst bucket capacity (mean deg 8; P(deg>64) ~ 1e-30)

// ---- k_feat tiling ----
#define FEAT_NODES 128
#define STT_STRIDE 136
#define OFF_STT 0
#define OFF_SW  (64 * STT_STRIDE)
#define OFF_SWN (OFF_SW  + 4096)
#define OFF_SWC (OFF_SWN + 640)
#define OFF_SBN (OFF_SWC + 384)
#define OFF_SBC (OFF_SBN + 32)
#define OFF_SBT (OFF_SBC + 32)
#define OFF_SL  (OFF_SBT + 64)
#define OFF_SR  (OFF_SL  + 64)
#define FEAT_SMEM ((OFF_SR + 64) * 4)   // 56320 bytes

// ---------------- scratch (static device allocations; allowed) ----------------
__device__ float  g_x [(size_t)NN*DD];
__device__ float  g_x1[(size_t)NN*DD];
__device__ float  g_x2[(size_t)NN*DD];
__device__ int    g_cursor[NN];
__device__ int    g_slots[(size_t)NN * CAP];   // bucketed CSR: src per slot
__device__ float2 g_sd_a[NN];   // (al, dinv)
__device__ float2 g_sd_b[NN];
__device__ float  g_ar_a[NN];
__device__ float  g_ar_b[NN];
__device__ int    g_is32;

__device__ __forceinline__ float lrelu(float v) { return v > 0.f ? v : 0.01f * v; }

__device__ __forceinline__ int load_idx(const void* p, long long i) {
    if (g_is32) return ((const int*)p)[i];
    return (int)(((const long long*)p)[i]);
}

// ---- packed f32x2 helpers (FFMA2; IEEE-identical to scalar FFMA) ----
__device__ __forceinline__ unsigned long long pack2(float lo, float hi) {
    unsigned long long r;
    asm("mov.b64 %0, {%1, %2};" : "=l"(r) : "f"(lo), "f"(hi));
    return r;
}
__device__ __forceinline__ unsigned long long ffma2(unsigned long long a,
                                                    unsigned long long b,
                                                    unsigned long long c) {
    unsigned long long d;
    asm("fma.rn.f32x2 %0, %1, %2, %3;" : "=l"(d) : "l"(a), "l"(b), "l"(c));
    return d;
}
__device__ __forceinline__ float2 unpack2(unsigned long long v) {
    float2 r;
    asm("mov.b64 {%0, %1}, %2;" : "=f"(r.x), "=f"(r.y) : "l"(v));
    return r;
}

// ---------------- init: dtype detection + cursor zeroing (merged) ----------------
__global__ void k_init(const void* ei) {
    int i = blockIdx.x * blockDim.x + threadIdx.x;
    if (i < NN) g_cursor[i] = 0;
    if (i == 0) {
        const unsigned long long* p = (const unsigned long long*)ei;
        int is32 = 0;
        for (int k = 0; k < 64; k++)
            if (p[k] > 0xFFFFFFFFull) is32 = 1;
        g_is32 = is32;
    }
}

// ---------------- bucket scatter: one edge per thread ----------------
__global__ void k_scatter(const void* __restrict__ ei) {
    int e = blockIdx.x * blockDim.x + threadIdx.x;
    if (e >= EE) return;
    int s = load_idx(ei, e);
    int d = load_idx(ei, (long long)EE + e);
    int pos = atomicAdd(&g_cursor[d], 1);
    if (pos < CAP) g_slots[(size_t)d * CAP + pos] = s;
}

// ---------------- feature MLP: 256 threads, 4x8 tile, FFMA2 stage 2 ----------------
// Stage 1: t<128 -> num half (dims 0:32) of node base+t; t>=128 -> cat half
// (dims 32:64) of node base+(t-128). Stage 2: thread tile 4 nodes x 8 dims.
__global__ __launch_bounds__(256) void k_feat(
        const float* __restrict__ numP, const float* __restrict__ catP,
        const float* __restrict__ Wn, const float* __restrict__ bn,
        const float* __restrict__ Wc, const float* __restrict__ bc,
        const float* __restrict__ Wt, const float* __restrict__ bt,
        const float* __restrict__ attL, const float* __restrict__ attR) {
    extern __shared__ float sm[];
    float*  stT = sm + OFF_STT;
    float4* sW4 = (float4*)(sm + OFF_SW);
    float4* sWn4 = (float4*)(sm + OFF_SWN);
    float4* sWc4 = (float4*)(sm + OFF_SWC);
    float4* sbn4 = (float4*)(sm + OFF_SBN);
    float4* sbc4 = (float4*)(sm + OFF_SBC);
    float4* sbt4 = (float4*)(sm + OFF_SBT);
    float4* sL4  = (float4*)(sm + OFF_SL);
    float4* sR4  = (float4*)(sm + OFF_SR);

    int t = threadIdx.x;
    for (int i = t; i < 1024; i += 256) sW4[i]  = ((const float4*)Wt)[i];
    for (int i = t; i < 160;  i += 256) sWn4[i] = ((const float4*)Wn)[i];
    for (int i = t; i < 96;   i += 256) sWc4[i] = ((const float4*)Wc)[i];
    if (t < 8)        sbn4[t]      = ((const float4*)bn)[t];
    else if (t < 16)  sbc4[t - 8]  = ((const float4*)bc)[t - 8];
    else if (t < 32)  sbt4[t - 16] = ((const float4*)bt)[t - 16];
    else if (t < 48)  sL4[t - 32]  = ((const float4*)attL)[t - 32];
    else if (t < 64)  sR4[t - 48]  = ((const float4*)attR)[t - 48];
    __syncthreads();

    int base = blockIdx.x * FEAT_NODES;

    // ---- stage 1: each half-block computes one 32-dim half ----
    {
        int m = t & 127;
        int node = base + m;
        if (node < NN) {
            if (t < 128) {
                float inf[20];
                const float4* nr = (const float4*)(numP + (size_t)node * 20);
                #pragma unroll
                for (int q = 0; q < 5; q++) {
                    float4 v = __ldg(nr + q);
                    inf[4*q] = v.x; inf[4*q+1] = v.y; inf[4*q+2] = v.z; inf[4*q+3] = v.w;
                }
                #pragma unroll
                for (int g = 0; g < 8; g++) {
                    float4 a = sbn4[g];
                    #pragma unroll
                    for (int k = 0; k < 20; k++) {
                        float4 w = sWn4[k * 8 + g];
                        a.x += inf[k] * w.x; a.y += inf[k] * w.y;
                        a.z += inf[k] * w.z; a.w += inf[k] * w.w;
                    }
                    stT[(4*g + 0) * STT_STRIDE + m] = lrelu(a.x);
                    stT[(4*g + 1) * STT_STRIDE + m] = lrelu(a.y);
                    stT[(4*g + 2) * STT_STRIDE + m] = lrelu(a.z);
                    stT[(4*g + 3) * STT_STRIDE + m] = lrelu(a.w);
                }
            } else {
                float inf[12];
                const float4* cr = (const float4*)(catP + (size_t)node * 12);
                #pragma unroll
                for (int q = 0; q < 3; q++) {
                    float4 v = __ldg(cr + q);
                    inf[4*q] = v.x; inf[4*q+1] = v.y; inf[4*q+2] = v.z; inf[4*q+3] = v.w;
                }
                #pragma unroll
                for (int g = 0; g < 8; g++) {
                    float4 a = sbc4[g];
                    #pragma unroll
                    for (int k = 0; k < 12; k++) {
                        float4 w = sWc4[k * 8 + g];
                        a.x += inf[k] * w.x; a.y += inf[k] * w.y;
                        a.z += inf[k] * w.z; a.w += inf[k] * w.w;
                    }
                    stT[(32 + 4*g + 0) * STT_STRIDE + m] = lrelu(a.x);
                    stT[(32 + 4*g + 1) * STT_STRIDE + m] = lrelu(a.y);
                    stT[(32 + 4*g + 2) * STT_STRIDE + m] = lrelu(a.z);
                    stT[(32 + 4*g + 3) * STT_STRIDE + m] = lrelu(a.w);
                }
            }
        } else {
            // zero this node's rows (own half only)
            int r0 = (t < 128) ? 0 : 32;
            for (int r = r0; r < r0 + 32; r++) stT[r * STT_STRIDE + m] = 0.f;
        }
    }
    __syncthreads();

    // ---- stage 2: GEMM, thread tile 4 nodes x 8 dims, packed FFMA2 ----
    int tm = t >> 3;   // 0..31 -> node group of 4
    int tn = t & 7;    // 0..7  -> dim group of 8
    unsigned long long acc2[4][4];
    {
        float4 b0 = sbt4[tn * 2], b1 = sbt4[tn * 2 + 1];
        unsigned long long p0 = pack2(b0.x, b0.y), p1 = pack2(b0.z, b0.w);
        unsigned long long p2 = pack2(b1.x, b1.y), p3 = pack2(b1.z, b1.w);
        #pragma unroll
        for (int j = 0; j < 4; j++) {
            acc2[j][0] = p0; acc2[j][1] = p1; acc2[j][2] = p2; acc2[j][3] = p3;
        }
    }
    const ulonglong2* sW2 = (const ulonglong2*)(sm + OFF_SW);
    #pragma unroll 4
    for (int k = 0; k < 64; k++) {
        float4 a = *(const float4*)(stT + k * STT_STRIDE + tm * 4);
        ulonglong2 bb0 = sW2[k * 16 + tn * 2];
        ulonglong2 bb1 = sW2[k * 16 + tn * 2 + 1];
        float av[4] = {a.x, a.y, a.z, a.w};
        #pragma unroll
        for (int j = 0; j < 4; j++) {
            unsigned long long a2 = pack2(av[j], av[j]);
            acc2[j][0] = ffma2(a2, bb0.x, acc2[j][0]);
            acc2[j][1] = ffma2(a2, bb0.y, acc2[j][1]);
            acc2[j][2] = ffma2(a2, bb1.x, acc2[j][2]);
            acc2[j][3] = ffma2(a2, bb1.y, acc2[j][3]);
        }
    }

    // ---- epilogue: unpack + lrelu + dots + dinv + stores ----
    float4 L0 = sL4[tn * 2], L1 = sL4[tn * 2 + 1];
    float4 R0 = sR4[tn * 2], R1 = sR4[tn * 2 + 1];
    #pragma unroll
    for (int j = 0; j < 4; j++) {
        int node = base + tm * 4 + j;
        float2 q0 = unpack2(acc2[j][0]);
        float2 q1 = unpack2(acc2[j][1]);
        float2 q2 = unpack2(acc2[j][2]);
        float2 q3 = unpack2(acc2[j][3]);
        float4 v0 = make_float4(q0.x, q0.y, q1.x, q1.y);
        float4 v1 = make_float4(q2.x, q2.y, q3.x, q3.y);
        v0.x = lrelu(v0.x); v0.y = lrelu(v0.y); v0.z = lrelu(v0.z); v0.w = lrelu(v0.w);
        v1.x = lrelu(v1.x); v1.y = lrelu(v1.y); v1.z = lrelu(v1.z); v1.w = lrelu(v1.w);
        float alp = v0.x*L0.x + v0.y*L0.y + v0.z*L0.z + v0.w*L0.w
                  + v1.x*L1.x + v1.y*L1.y + v1.z*L1.z + v1.w*L1.w;
        float arp = v0.x*R0.x + v0.y*R0.y + v0.z*R0.z + v0.w*R0.w
                  + v1.x*R1.x + v1.y*R1.y + v1.z*R1.z + v1.w*R1.w;
        #pragma unroll
        for (int o = 1; o < 8; o <<= 1) {
            alp += __shfl_xor_sync(0xffffffffu, alp, o);
            arp += __shfl_xor_sync(0xffffffffu, arp, o);
        }
        if (node < NN) {
            float4* xrow = (float4*)(g_x + (size_t)node * 64);
            xrow[tn * 2]     = v0;
            xrow[tn * 2 + 1] = v1;
            if (tn == 0) {
                float dinv = rsqrtf((float)(g_cursor[node] + 1));
                g_sd_a[node] = make_float2(alp, dinv);
                g_ar_a[node] = arp;
            }
        }
    }
}

// ---------------- FAConv gather: TWO dsts per warp, 16 lanes each ----------------
template <int DO_ABS, int DO_DOTS>
__global__ __launch_bounds__(64) void k_gather(
                         const float* __restrict__ h, const float* __restrict__ h0,
                         const float2* __restrict__ sd_in, const float* __restrict__ ar_in,
                         float* __restrict__ out,
                         float2* __restrict__ sd_out, float* __restrict__ ar_out,
                         const float* __restrict__ attL, const float* __restrict__ attR) {
    int warp = blockIdx.x * 2 + (threadIdx.x >> 5);
    int lane = threadIdx.x & 31;
    int half = lane >> 4;
    int sub  = lane & 15;
    int d    = warp * 2 + half;

    bool valid = (d < NN);
    int dd = valid ? d : (NN - 1);        // safe index; stores masked by valid

    int cnt = valid ? g_cursor[dd] : 0;
    if (cnt > CAP) cnt = CAP;
    int ocnt = __shfl_xor_sync(0xffffffffu, cnt, 16);   // single convergent shfl
    int cntmax = cnt > ocnt ? cnt : ocnt;               // warp-uniform

    const int* slots = g_slots + (size_t)dd * CAP;
    float2 sdd = __ldg(&sd_in[dd]);
    float ar_d = __ldg(&ar_in[dd]);
    float dv_d = sdd.y;

    float4 acc = make_float4(0.f, 0.f, 0.f, 0.f);
    for (int cb = 0; cb < cntmax; cb += 16) {
        int n = cnt - cb;                 // may be <= 0 for this half
        int s = 0; float alpha = 0.f;
        if (sub < n) {
            s = __ldg(&slots[cb + sub]);
            float2 sd = __ldg(&sd_in[s]);
            alpha = tanhf(sd.x + ar_d) * sd.y * dv_d;
        }
        int nw = cntmax - cb; if (nw > 16) nw = 16;
        for (int t = 0; t < nw; t++) {
            int src = 16 * half + t;      // own half's lane t
            int   sj = __shfl_sync(0xffffffffu, s, src);
            float aj = __shfl_sync(0xffffffffu, alpha, src);
            float4 hv = __ldg((const float4*)(h + (size_t)sj * 64) + sub);
            acc.x += aj * hv.x; acc.y += aj * hv.y;
            acc.z += aj * hv.z; acc.w += aj * hv.w;
        }
    }

    if (valid) {
        float aself = tanhf(sdd.x + ar_d) * dv_d * dv_d;
        float4 hd  = __ldg((const float4*)(h  + (size_t)d * 64) + sub);
        float4 h0v = __ldg((const float4*)(h0 + (size_t)d * 64) + sub);
        acc.x += aself * hd.x + EPS * h0v.x;
        acc.y += aself * hd.y + EPS * h0v.y;
        acc.z += aself * hd.z + EPS * h0v.z;
        acc.w += aself * hd.w + EPS * h0v.w;
        if (DO_ABS) {
            acc.x = sqrtf(acc.x * acc.x + 1e-8f);
            acc.y = sqrtf(acc.y * acc.y + 1e-8f);
            acc.z = sqrtf(acc.z * acc.z + 1e-8f);
            acc.w = sqrtf(acc.w * acc.w + 1e-8f);
        }
        ((float4*)(out + (size_t)d * 64))[sub] = acc;

        if (DO_DOTS) {
            float4 L = __ldg((const float4*)attL + sub);
            float4 R = __ldg((const float4*)attR + sub);
            float a = acc.x * L.x + acc.y * L.y + acc.z * L.z + acc.w * L.w;
            float b = acc.x * R.x + acc.y * R.y + acc.z * R.z + acc.w * R.w;
            #pragma unroll
            for (int o = 1; o < 16; o <<= 1) {   // reduce within 16-lane half
                a += __shfl_xor_sync(0xffffffffu, a, o);
                b += __shfl_xor_sync(0xffffffffu, b, o);
            }
            if (sub == 0) {
                sd_out[d] = make_float2(a, dv_d);
                ar_out[d] = b;
            }
        }
    }
}

// ---------------- fused per-user segment sum + head ----------------
// One warp per output user u: g = re[u]; segment-sum x2 rows offs[g]..offs[g+1]
// (duplicated g's recomputed), then head inline. No x3 buffer.
__global__ void k_uf(const void* __restrict__ offs, const void* __restrict__ re,
                     const float* __restrict__ x2v,
                     const float* __restrict__ Wf, const float* __restrict__ bf,
                     const float* __restrict__ Wl, const float* __restrict__ bl,
                     float* __restrict__ out) {
    int u = blockIdx.x * 8 + (threadIdx.x >> 5);
    if (u >= UU) return;
    int lane = threadIdx.x & 31;
    int half = lane >> 4;
    int sub  = lane & 15;

    int g  = load_idx(re, u);
    int s0 = load_idx(offs, g);
    int s1 = load_idx(offs, g + 1);
    if (s0 < 0) s0 = 0;
    if (s1 > NN) s1 = NN;

    float4 acc = make_float4(0.f, 0.f, 0.f, 0.f);
    for (int r = s0 + half; r < s1; r += 2) {
        float4 v = __ldg((const float4*)(x2v + (size_t)r * 64) + sub);
        acc.x += v.x; acc.y += v.y; acc.z += v.z; acc.w += v.w;
    }
    // cross-half reduce: afterwards EVERY lane holds the full sum for dims
    // 4*sub .. 4*sub+3 (halves are mirrors)
    acc.x += __shfl_xor_sync(0xffffffffu, acc.x, 16);
    acc.y += __shfl_xor_sync(0xffffffffu, acc.y, 16);
    acc.z += __shfl_xor_sync(0xffffffffu, acc.z, 16);
    acc.w += __shfl_xor_sync(0xffffffffu, acc.w, 16);

    // head: lane j owns hidden dim j; x3 value for dim 4q+c lives in lane q
    float hj = bf[lane];
    #pragma unroll
    for (int q = 0; q < 16; q++) {
        float a = __shfl_sync(0xffffffffu, acc.x, q);
        float b = __shfl_sync(0xffffffffu, acc.y, q);
        float c = __shfl_sync(0xffffffffu, acc.z, q);
        float dv = __shfl_sync(0xffffffffu, acc.w, q);
        hj += a  * Wf[(4*q + 0) * 32 + lane]
            + b  * Wf[(4*q + 1) * 32 + lane]
            + c  * Wf[(4*q + 2) * 32 + lane]
            + dv * Wf[(4*q + 3) * 32 + lane];
    }
    hj = lrelu(hj);
    float o0 = hj * Wl[lane * 2];
    float o1 = hj * Wl[lane * 2 + 1];
    #pragma unroll
    for (int o = 16; o; o >>= 1) {
        o0 += __shfl_xor_sync(0xffffffffu, o0, o);
        o1 += __shfl_xor_sync(0xffffffffu, o1, o);
    }
    if (lane == 0) {
        out[(size_t)u * 2]     = o0 + bl[0];
        out[(size_t)u * 2 + 1] = o1 + bl[1];
    }
}

// ---------------- launch ----------------
extern "C" void kernel_launch(void* const* d_in, const int* in_sizes, int n_in,
                              void* d_out, int out_size) {
    const float* num_prop = (const float*)d_in[0];
    const float* cat_prop = (const float*)d_in[1];
    const void*  offs     = d_in[2];
    const void*  ei       = d_in[3];
    const void*  re       = d_in[4];
    const float* W_num = (const float*)d_in[5];
    const float* b_num = (const float*)d_in[6];
    const float* W_cat = (const float*)d_in[7];
    const float* b_cat = (const float*)d_in[8];
    const float* W_tog = (const float*)d_in[9];
    const float* b_tog = (const float*)d_in[10];
    const float* att_l = (const float*)d_in[11];
    const float* att_r = (const float*)d_in[12];
    const float* W_f1  = (const float*)d_in[13];
    const float* b_f1  = (const float*)d_in[14];
    const float* W_lab = (const float*)d_in[15];
    const float* b_lab = (const float*)d_in[16];
    float* out = (float*)d_out;

    float *x, *x1, *x2;
    float2 *sda, *sdb;
    float *ara, *arb;
    cudaGetSymbolAddress((void**)&x,   g_x);
    cudaGetSymbolAddress((void**)&x1,  g_x1);
    cudaGetSymbolAddress((void**)&x2,  g_x2);
    cudaGetSymbolAddress((void**)&sda, g_sd_a);
    cudaGetSymbolAddress((void**)&sdb, g_sd_b);
    cudaGetSymbolAddress((void**)&ara, g_ar_a);
    cudaGetSymbolAddress((void**)&arb, g_ar_b);

    cudaFuncSetAttribute(k_feat, cudaFuncAttributeMaxDynamicSharedMemorySize, FEAT_SMEM);

    const int T = 256;
    const int GW = (NN + 3) / 4;   // gather blocks: 4 dsts per block (2 warps x 2)

    // 1: dtype detect + cursor zero
    k_init<<<(NN + T - 1) / T, T>>>(ei);
    // 2: bucket scatter (1 edge/thread)
    k_scatter<<<(EE + T - 1) / T, T>>>(ei);
    // 3: features + fused layer-A dots + dinv
    k_feat<<<(NN + FEAT_NODES - 1) / FEAT_NODES, 256, FEAT_SMEM>>>(
        num_prop, cat_prop, W_num, b_num, W_cat, b_cat, W_tog, b_tog, att_l, att_r);
    // 4: FAConv layer 1 (fused combine + next-layer dots) — profiled launch slot
    k_gather<0, 1><<<GW, 64>>>(x, x, sda, ara, x1, sdb, arb, att_l, att_r);
    // 5: FAConv layer 2 (fused combine + smooth-abs)
    k_gather<1, 0><<<GW, 64>>>(x1, x, sdb, arb, x2, nullptr, nullptr, att_l, att_r);
    // 6: fused per-user segment sum + head
    k_uf<<<(UU + 7) / 8, 256>>>(offs, re, x2, W_f1, b_f1, W_lab, b_lab, out);
}

// round 17
// speedup vs baseline: 1.0567x; 1.0567x over previous
#include <cuda_runtime.h>

// Problem constants (fixed for this problem instance)
#define NN 200000
#define EE 1600000
#define UU 20000
#define DD 64
#define EPS 0.1f

#define CAP 64   // per-dst bucket capacity (mean deg 8; P(deg>64) ~ 1e-30)

// ---- k_feat tiling ----
#define FEAT_NODES 128
#define STT_STRIDE 136
#define OFF_STT 0
#define OFF_SW  (64 * STT_STRIDE)
#define OFF_SWN (OFF_SW  + 4096)
#define OFF_SWC (OFF_SWN + 640)
#define OFF_SBN (OFF_SWC + 384)
#define OFF_SBC (OFF_SBN + 32)
#define OFF_SBT (OFF_SBC + 32)
#define OFF_SL  (OFF_SBT + 64)
#define OFF_SR  (OFF_SL  + 64)
#define FEAT_SMEM ((OFF_SR + 64) * 4)   // 56320 bytes

// ---------------- scratch (static device allocations; allowed) ----------------
__device__ float  g_x [(size_t)NN*DD];
__device__ float  g_x1[(size_t)NN*DD];
__device__ float  g_x2[(size_t)NN*DD];
__device__ int    g_cursor[NN];
__device__ int    g_slots[(size_t)NN * CAP];   // bucketed CSR: src per slot
__device__ float2 g_sd_a[NN];   // (al, dinv)
__device__ float2 g_sd_b[NN];
__device__ float  g_ar_a[NN];
__device__ float  g_ar_b[NN];
__device__ float  g_x3[(size_t)UU*DD];
__device__ int    g_is32;

__device__ __forceinline__ float lrelu(float v) { return v > 0.f ? v : 0.01f * v; }

__device__ __forceinline__ int load_idx(const void* p, long long i) {
    if (g_is32) return ((const int*)p)[i];
    return (int)(((const long long*)p)[i]);
}

// ---------------- init: dtype detection + cursor zeroing ----------------
__global__ void k_init(const void* ei) {
    int i = blockIdx.x * blockDim.x + threadIdx.x;
    if (i < NN) g_cursor[i] = 0;
    if (i == 0) {
        const unsigned long long* p = (const unsigned long long*)ei;
        int is32 = 0;
        for (int k = 0; k < 64; k++)
            if (p[k] > 0xFFFFFFFFull) is32 = 1;
        g_is32 = is32;
    }
}

// ---------------- bucket scatter: one edge per thread ----------------
__global__ void k_scatter(const void* __restrict__ ei) {
    int e = blockIdx.x * blockDim.x + threadIdx.x;
    if (e >= EE) return;
    int s = load_idx(ei, e);
    int d = load_idx(ei, (long long)EE + e);
    int pos = atomicAdd(&g_cursor[d], 1);
    if (pos < CAP) g_slots[(size_t)d * CAP + pos] = s;
}

// ---------------- feature MLP: smem-tiled GEMM, 8x8 thread tile (round-13 form) ----------------
__global__ __launch_bounds__(128) void k_feat(
        const float* __restrict__ numP, const float* __restrict__ catP,
        const float* __restrict__ Wn, const float* __restrict__ bn,
        const float* __restrict__ Wc, const float* __restrict__ bc,
        const float* __restrict__ Wt, const float* __restrict__ bt,
        const float* __restrict__ attL, const float* __restrict__ attR) {
    extern __shared__ float sm[];
    float*  stT = sm + OFF_STT;
    float4* sW4 = (float4*)(sm + OFF_SW);
    float4* sWn4 = (float4*)(sm + OFF_SWN);
    float4* sWc4 = (float4*)(sm + OFF_SWC);
    float4* sbn4 = (float4*)(sm + OFF_SBN);
    float4* sbc4 = (float4*)(sm + OFF_SBC);
    float4* sbt4 = (float4*)(sm + OFF_SBT);
    float4* sL4  = (float4*)(sm + OFF_SL);
    float4* sR4  = (float4*)(sm + OFF_SR);

    int t = threadIdx.x;
    for (int i = t; i < 1024; i += 128) sW4[i]  = ((const float4*)Wt)[i];
    for (int i = t; i < 160;  i += 128) sWn4[i] = ((const float4*)Wn)[i];
    for (int i = t; i < 96;   i += 128) sWc4[i] = ((const float4*)Wc)[i];
    if (t < 8)        sbn4[t]      = ((const float4*)bn)[t];
    else if (t < 16)  sbc4[t - 8]  = ((const float4*)bc)[t - 8];
    else if (t < 32)  sbt4[t - 16] = ((const float4*)bt)[t - 16];
    else if (t < 48)  sL4[t - 32]  = ((const float4*)attL)[t - 32];
    else if (t < 64)  sR4[t - 48]  = ((const float4*)attR)[t - 48];
    __syncthreads();

    int base = blockIdx.x * FEAT_NODES;
    int node1 = base + t;

    // ---- stage 1: full hidden vector per thread ----
    if (node1 < NN) {
        {
            float inf[20];
            const float4* nr = (const float4*)(numP + (size_t)node1 * 20);
            #pragma unroll
            for (int q = 0; q < 5; q++) {
                float4 v = __ldg(nr + q);
                inf[4*q] = v.x; inf[4*q+1] = v.y; inf[4*q+2] = v.z; inf[4*q+3] = v.w;
            }
            #pragma unroll
            for (int g = 0; g < 8; g++) {
                float4 a = sbn4[g];
                #pragma unroll
                for (int k = 0; k < 20; k++) {
                    float4 w = sWn4[k * 8 + g];
                    a.x += inf[k] * w.x; a.y += inf[k] * w.y;
                    a.z += inf[k] * w.z; a.w += inf[k] * w.w;
                }
                stT[(4*g + 0) * STT_STRIDE + t] = lrelu(a.x);
                stT[(4*g + 1) * STT_STRIDE + t] = lrelu(a.y);
                stT[(4*g + 2) * STT_STRIDE + t] = lrelu(a.z);
                stT[(4*g + 3) * STT_STRIDE + t] = lrelu(a.w);
            }
        }
        {
            float inf[12];
            const float4* cr = (const float4*)(catP + (size_t)node1 * 12);
            #pragma unroll
            for (int q = 0; q < 3; q++) {
                float4 v = __ldg(cr + q);
                inf[4*q] = v.x; inf[4*q+1] = v.y; inf[4*q+2] = v.z; inf[4*q+3] = v.w;
            }
            #pragma unroll
            for (int g = 0; g < 8; g++) {
                float4 a = sbc4[g];
                #pragma unroll
                for (int k = 0; k < 12; k++) {
                    float4 w = sWc4[k * 8 + g];
                    a.x += inf[k] * w.x; a.y += inf[k] * w.y;
                    a.z += inf[k] * w.z; a.w += inf[k] * w.w;
                }
                stT[(32 + 4*g + 0) * STT_STRIDE + t] = lrelu(a.x);
                stT[(32 + 4*g + 1) * STT_STRIDE + t] = lrelu(a.y);
                stT[(32 + 4*g + 2) * STT_STRIDE + t] = lrelu(a.z);
                stT[(32 + 4*g + 3) * STT_STRIDE + t] = lrelu(a.w);
            }
        }
    } else {
        for (int r = 0; r < 64; r++) stT[r * STT_STRIDE + t] = 0.f;
    }
    __syncthreads();

    // ---- stage 2: GEMM, thread tile 8 nodes x 8 dims ----
    int tm = t >> 3;
    int tn = t & 7;
    float4 acc[8][2];
    {
        float4 b0 = sbt4[tn * 2], b1 = sbt4[tn * 2 + 1];
        #pragma unroll
        for (int j = 0; j < 8; j++) { acc[j][0] = b0; acc[j][1] = b1; }
    }
    #pragma unroll 2
    for (int k = 0; k < 64; k++) {
        const float4* arow = (const float4*)(stT + k * STT_STRIDE + tm * 8);
        float4 a0 = arow[0];
        float4 a1 = arow[1];
        float4 b0 = sW4[k * 16 + tn * 2];
        float4 b1 = sW4[k * 16 + tn * 2 + 1];
        float av[8] = {a0.x, a0.y, a0.z, a0.w, a1.x, a1.y, a1.z, a1.w};
        #pragma unroll
        for (int j = 0; j < 8; j++) {
            acc[j][0].x += av[j]*b0.x; acc[j][0].y += av[j]*b0.y;
            acc[j][0].z += av[j]*b0.z; acc[j][0].w += av[j]*b0.w;
            acc[j][1].x += av[j]*b1.x; acc[j][1].y += av[j]*b1.y;
            acc[j][1].z += av[j]*b1.z; acc[j][1].w += av[j]*b1.w;
        }
    }

    // ---- epilogue: lrelu + dots + dinv + stores ----
    float4 L0 = sL4[tn * 2], L1 = sL4[tn * 2 + 1];
    float4 R0 = sR4[tn * 2], R1 = sR4[tn * 2 + 1];
    #pragma unroll
    for (int j = 0; j < 8; j++) {
        int node = base + tm * 8 + j;
        float4 v0 = acc[j][0], v1 = acc[j][1];
        v0.x = lrelu(v0.x); v0.y = lrelu(v0.y); v0.z = lrelu(v0.z); v0.w = lrelu(v0.w);
        v1.x = lrelu(v1.x); v1.y = lrelu(v1.y); v1.z = lrelu(v1.z); v1.w = lrelu(v1.w);
        float alp = v0.x*L0.x + v0.y*L0.y + v0.z*L0.z + v0.w*L0.w
                  + v1.x*L1.x + v1.y*L1.y + v1.z*L1.z + v1.w*L1.w;
        float arp = v0.x*R0.x + v0.y*R0.y + v0.z*R0.z + v0.w*R0.w
                  + v1.x*R1.x + v1.y*R1.y + v1.z*R1.z + v1.w*R1.w;
        #pragma unroll
        for (int o = 1; o < 8; o <<= 1) {
            alp += __shfl_xor_sync(0xffffffffu, alp, o);
            arp += __shfl_xor_sync(0xffffffffu, arp, o);
        }
        if (node < NN) {
            float4* xrow = (float4*)(g_x + (size_t)node * 64);
            xrow[tn * 2]     = v0;
            xrow[tn * 2 + 1] = v1;
            if (tn == 0) {
                float dinv = rsqrtf((float)(g_cursor[node] + 1));
                g_sd_a[node] = make_float2(alp, dinv);
                g_ar_a[node] = arp;
            }
        }
    }
}

// ---------------- FAConv gather: TWO dsts per warp, 16 lanes each ----------------
// SAME_H0=1 (layer 1): h == h0, so h0's row is reused from hd (one LDG saved).
template <int DO_ABS, int DO_DOTS, int SAME_H0>
__global__ __launch_bounds__(64) void k_gather(
                         const float* __restrict__ h, const float* __restrict__ h0,
                         const float2* __restrict__ sd_in, const float* __restrict__ ar_in,
                         float* __restrict__ out,
                         float2* __restrict__ sd_out, float* __restrict__ ar_out,
                         const float* __restrict__ attL, const float* __restrict__ attR) {
    int warp = blockIdx.x * 2 + (threadIdx.x >> 5);
    int lane = threadIdx.x & 31;
    int half = lane >> 4;
    int sub  = lane & 15;
    int d    = warp * 2 + half;

    bool valid = (d < NN);
    int dd = valid ? d : (NN - 1);        // safe index; stores masked by valid

    int cnt = valid ? g_cursor[dd] : 0;
    if (cnt > CAP) cnt = CAP;
    int ocnt = __shfl_xor_sync(0xffffffffu, cnt, 16);   // single convergent shfl
    int cntmax = cnt > ocnt ? cnt : ocnt;               // warp-uniform

    const int* slots = g_slots + (size_t)dd * CAP;
    float2 sdd = __ldg(&sd_in[dd]);
    float ar_d = __ldg(&ar_in[dd]);
    float dv_d = sdd.y;

    float4 acc = make_float4(0.f, 0.f, 0.f, 0.f);
    for (int cb = 0; cb < cntmax; cb += 16) {
        int n = cnt - cb;                 // may be <= 0 for this half
        int s = 0; float alpha = 0.f;
        if (sub < n) {
            s = __ldg(&slots[cb + sub]);
            float2 sd = __ldg(&sd_in[s]);
            alpha = tanhf(sd.x + ar_d) * sd.y * dv_d;
        }
        int nw = cntmax - cb; if (nw > 16) nw = 16;
        for (int t = 0; t < nw; t++) {
            int src = 16 * half + t;      // own half's lane t
            int   sj = __shfl_sync(0xffffffffu, s, src);
            float aj = __shfl_sync(0xffffffffu, alpha, src);
            float4 hv = __ldg((const float4*)(h + (size_t)sj * 64) + sub);
            acc.x += aj * hv.x; acc.y += aj * hv.y;
            acc.z += aj * hv.z; acc.w += aj * hv.w;
        }
    }

    if (valid) {
        float aself = tanhf(sdd.x + ar_d) * dv_d * dv_d;
        float4 hd  = __ldg((const float4*)(h + (size_t)d * 64) + sub);
        float4 h0v;
        if (SAME_H0) h0v = hd;
        else         h0v = __ldg((const float4*)(h0 + (size_t)d * 64) + sub);
        acc.x += aself * hd.x + EPS * h0v.x;
        acc.y += aself * hd.y + EPS * h0v.y;
        acc.z += aself * hd.z + EPS * h0v.z;
        acc.w += aself * hd.w + EPS * h0v.w;
        if (DO_ABS) {
            acc.x = sqrtf(acc.x * acc.x + 1e-8f);
            acc.y = sqrtf(acc.y * acc.y + 1e-8f);
            acc.z = sqrtf(acc.z * acc.z + 1e-8f);
            acc.w = sqrtf(acc.w * acc.w + 1e-8f);
        }
        ((float4*)(out + (size_t)d * 64))[sub] = acc;

        if (DO_DOTS) {
            float4 L = __ldg((const float4*)attL + sub);
            float4 R = __ldg((const float4*)attR + sub);
            float a = acc.x * L.x + acc.y * L.y + acc.z * L.z + acc.w * L.w;
            float b = acc.x * R.x + acc.y * R.y + acc.z * R.z + acc.w * R.w;
            #pragma unroll
            for (int o = 1; o < 16; o <<= 1) {   // reduce within 16-lane half
                a += __shfl_xor_sync(0xffffffffu, a, o);
                b += __shfl_xor_sync(0xffffffffu, b, o);
            }
            if (sub == 0) {
                sd_out[d] = make_float2(a, dv_d);
                ar_out[d] = b;
            }
        }
    }
}

// ---------------- per-user segment sum: direct CSR gather ----------------
__global__ void k_user(const void* __restrict__ offs, const float* __restrict__ x2v) {
    int u = blockIdx.x * 8 + (threadIdx.x >> 5);
    if (u >= UU) return;
    int lane = threadIdx.x & 31;
    int half = lane >> 4;
    int sub  = lane & 15;
    int s0 = load_idx(offs, u);
    int s1 = load_idx(offs, u + 1);
    if (s0 < 0) s0 = 0;
    if (s1 > NN) s1 = NN;
    float4 acc = make_float4(0.f, 0.f, 0.f, 0.f);
    for (int r = s0 + half; r < s1; r += 2) {
        float4 v = __ldg((const float4*)(x2v + (size_t)r * 64) + sub);
        acc.x += v.x; acc.y += v.y; acc.z += v.z; acc.w += v.w;
    }
    acc.x += __shfl_xor_sync(0xffffffffu, acc.x, 16);
    acc.y += __shfl_xor_sync(0xffffffffu, acc.y, 16);
    acc.z += __shfl_xor_sync(0xffffffffu, acc.z, 16);
    acc.w += __shfl_xor_sync(0xffffffffu, acc.w, 16);
    if (half == 0)
        ((float4*)(g_x3 + (size_t)u * 64))[sub] = acc;
}

// ---------------- head ----------------
__global__ void k_final(const void* __restrict__ re,
                        const float* __restrict__ Wf, const float* __restrict__ bf,
                        const float* __restrict__ Wl, const float* __restrict__ bl,
                        float* __restrict__ out) {
    int idx = blockIdx.x * blockDim.x + threadIdx.x;
    int u = idx >> 5;
    if (u >= UU) return;
    int j = idx & 31;
    int g = load_idx(re, u);
    float2 gv = ((const float2*)(g_x3 + (size_t)g * 64))[j];
    float hj = bf[j];
    #pragma unroll
    for (int k = 0; k < 32; k++) {
        float a = __shfl_sync(0xffffffffu, gv.x, k);
        float b = __shfl_sync(0xffffffffu, gv.y, k);
        hj += a * Wf[(2 * k) * 32 + j] + b * Wf[(2 * k + 1) * 32 + j];
    }
    hj = lrelu(hj);
    float o0 = hj * Wl[j * 2];
    float o1 = hj * Wl[j * 2 + 1];
    #pragma unroll
    for (int o = 16; o; o >>= 1) {
        o0 += __shfl_xor_sync(0xffffffffu, o0, o);
        o1 += __shfl_xor_sync(0xffffffffu, o1, o);
    }
    if (j == 0) {
        out[(size_t)u * 2]     = o0 + bl[0];
        out[(size_t)u * 2 + 1] = o1 + bl[1];
    }
}

// ---------------- launch ----------------
extern "C" void kernel_launch(void* const* d_in, const int* in_sizes, int n_in,
                              void* d_out, int out_size) {
    const float* num_prop = (const float*)d_in[0];
    const float* cat_prop = (const float*)d_in[1];
    const void*  offs     = d_in[2];
    const void*  ei       = d_in[3];
    const void*  re       = d_in[4];
    const float* W_num = (const float*)d_in[5];
    const float* b_num = (const float*)d_in[6];
    const float* W_cat = (const float*)d_in[7];
    const float* b_cat = (const float*)d_in[8];
    const float* W_tog = (const float*)d_in[9];
    const float* b_tog = (const float*)d_in[10];
    const float* att_l = (const float*)d_in[11];
    const float* att_r = (const float*)d_in[12];
    const float* W_f1  = (const float*)d_in[13];
    const float* b_f1  = (const float*)d_in[14];
    const float* W_lab = (const float*)d_in[15];
    const float* b_lab = (const float*)d_in[16];
    float* out = (float*)d_out;

    float *x, *x1, *x2;
    float2 *sda, *sdb;
    float *ara, *arb;
    cudaGetSymbolAddress((void**)&x,   g_x);
    cudaGetSymbolAddress((void**)&x1,  g_x1);
    cudaGetSymbolAddress((void**)&x2,  g_x2);
    cudaGetSymbolAddress((void**)&sda, g_sd_a);
    cudaGetSymbolAddress((void**)&sdb, g_sd_b);
    cudaGetSymbolAddress((void**)&ara, g_ar_a);
    cudaGetSymbolAddress((void**)&arb, g_ar_b);

    cudaFuncSetAttribute(k_feat, cudaFuncAttributeMaxDynamicSharedMemorySize, FEAT_SMEM);

    const int T = 256;
    const int GW = (NN + 3) / 4;   // gather blocks: 4 dsts per block (2 warps x 2)

    // 1: dtype detect + cursor zero
    k_init<<<(NN + T - 1) / T, T>>>(ei);
    // 2: bucket scatter (1 edge/thread)
    k_scatter<<<(EE + T - 1) / T, T>>>(ei);
    // 3: features + fused layer-A dots + dinv
    k_feat<<<(NN + FEAT_NODES - 1) / FEAT_NODES, 128, FEAT_SMEM>>>(
        num_prop, cat_prop, W_num, b_num, W_cat, b_cat, W_tog, b_tog, att_l, att_r);
    // 4: FAConv layer 1 (h == h0 -> SAME_H0=1; fused combine + next-layer dots)
    k_gather<0, 1, 1><<<GW, 64>>>(x, x, sda, ara, x1, sdb, arb, att_l, att_r);
    // 5: FAConv layer 2 (fused combine + smooth-abs)
    k_gather<1, 0, 0><<<GW, 64>>>(x1, x, sdb, arb, x2, nullptr, nullptr, att_l, att_r);
    // 6: per-user segment sum
    k_user<<<(UU + 7) / 8, 256>>>(offs, x2);
    // 7: head
    k_final<<<(UU * 32 + T - 1) / T, T>>>(re, W_f1, b_f1, W_lab, b_lab, out);
}